// round 11
// baseline (speedup 1.0000x reference)
#include <cuda_runtime.h>
#include <cuda_bf16.h>
#include <math.h>
#include <stdint.h>

// Problem constants
#define Bc 2
#define Tc 2048
#define Dc 1024
#define Hc 16
#define Lc 8
#define Ic 4096
#define HD 64
#define ROWS (Bc*Tc)
#define LN_EPS 1e-5f
#define MASK_BIAS -10000.0f

typedef __nv_bfloat16 bf16;

// ---------------- scratch -----------------------------------------------------
__device__ float  g_h[ROWS * Dc];                 // residual stream
__device__ bf16   g_qhi[ROWS * 3 * Dc], g_qlo[ROWS * 3 * Dc];  // qkv split (for attn)
__device__ float  g_ctx[ROWS * Dc];               // attention out fp32
__device__ float  g_act[ROWS * Ic];               // ffn inner fp32
// int8 activation digits + row scales
__device__ int8_t g_xq1[ROWS * Dc], g_xq2[ROWS * Dc];   __device__ float g_xs[ROWS];
__device__ int8_t g_cq1[ROWS * Dc], g_cq2[ROWS * Dc];   __device__ float g_cs[ROWS];
__device__ int8_t g_aq1[ROWS * Ic], g_aq2[ROWS * Ic];   __device__ float g_as[ROWS];
// int8 weight digits [l][N][K] + per-col scales [l][N]
__device__ int8_t g_wq1[Lc*3*Dc*Dc], g_wq2[Lc*3*Dc*Dc]; __device__ float g_wqs[Lc*3*Dc];
__device__ int8_t g_wp1[Lc*Dc*Dc],   g_wp2[Lc*Dc*Dc];   __device__ float g_wps[Lc*Dc];
__device__ int8_t g_wf1[Lc*Ic*Dc],   g_wf2[Lc*Ic*Dc];   __device__ float g_wfs[Lc*Ic];
__device__ int8_t g_wg1[Lc*Dc*Ic],   g_wg2[Lc*Dc*Ic];   __device__ float g_wgs[Lc*Dc];

// ---------------- utility ----------------------------------------------------
__inline__ __device__ float warp_sum(float v) {
    #pragma unroll
    for (int o = 16; o > 0; o >>= 1) v += __shfl_xor_sync(0xffffffffu, v, o);
    return v;
}
__inline__ __device__ float warp_max(float v) {
    #pragma unroll
    for (int o = 16; o > 0; o >>= 1) v = fmaxf(v, __shfl_xor_sync(0xffffffffu, v, o));
    return v;
}
__device__ __forceinline__ void split2(float v, bf16& hi, bf16& lo) {
    hi = __float2bfloat16(v);
    lo = __float2bfloat16(v - __bfloat162float(hi));
}
__device__ __forceinline__ void q2digit(float xs, int8_t& d1, int8_t& d2) {
    int a1 = __float2int_rn(xs);
    int a2 = __float2int_rn((xs - (float)a1) * 254.0f);
    d1 = (int8_t)a1; d2 = (int8_t)a2;
}

// ---------------- MMA / ldmatrix helpers --------------------------------------
__device__ __forceinline__ void ldsm4(unsigned* r, unsigned addr) {
    asm volatile("ldmatrix.sync.aligned.m8n8.x4.shared.b16 {%0,%1,%2,%3},[%4];"
        : "=r"(r[0]), "=r"(r[1]), "=r"(r[2]), "=r"(r[3]) : "r"(addr));
}
__device__ __forceinline__ void ldsm4t(unsigned* r, unsigned addr) {
    asm volatile("ldmatrix.sync.aligned.m8n8.x4.trans.shared.b16 {%0,%1,%2,%3},[%4];"
        : "=r"(r[0]), "=r"(r[1]), "=r"(r[2]), "=r"(r[3]) : "r"(addr));
}
__device__ __forceinline__ void mma16816(float* c, const unsigned* a, const unsigned* b) {
    asm volatile("mma.sync.aligned.m16n8k16.row.col.f32.bf16.bf16.f32 "
        "{%0,%1,%2,%3},{%4,%5,%6,%7},{%8,%9},{%0,%1,%2,%3};"
        : "+f"(c[0]), "+f"(c[1]), "+f"(c[2]), "+f"(c[3])
        : "r"(a[0]), "r"(a[1]), "r"(a[2]), "r"(a[3]), "r"(b[0]), "r"(b[1]));
}
__device__ __forceinline__ void imma(int* c, const unsigned* a, const unsigned* b) {
    asm volatile("mma.sync.aligned.m16n8k32.row.col.s32.s8.s8.s32 "
        "{%0,%1,%2,%3},{%4,%5,%6,%7},{%8,%9},{%0,%1,%2,%3};"
        : "+r"(c[0]), "+r"(c[1]), "+r"(c[2]), "+r"(c[3])
        : "r"(a[0]), "r"(a[1]), "r"(a[2]), "r"(a[3]), "r"(b[0]), "r"(b[1]));
}
__device__ __forceinline__ void cp_async16(unsigned saddr, const void* g) {
    asm volatile("cp.async.cg.shared.global [%0], [%1], 16;" :: "r"(saddr), "l"(g));
}
__device__ __forceinline__ unsigned smem_u32(const void* p) {
    return (unsigned)__cvta_generic_to_shared(p);
}
__device__ __forceinline__ void packsplit(float x, float y, unsigned& hi, unsigned& lo) {
    bf16 hx = __float2bfloat16(x);
    bf16 hy = __float2bfloat16(y);
    bf16 lx = __float2bfloat16(x - __bfloat162float(hx));
    bf16 ly = __float2bfloat16(y - __bfloat162float(hy));
    __nv_bfloat162 H(hx, hy), L(lx, ly);
    hi = *(unsigned*)&H; lo = *(unsigned*)&L;
}

// ---------------- small kernels -----------------------------------------------
__global__ void copy_kernel(const float* __restrict__ src, float* __restrict__ dst, int n) {
    int i = blockIdx.x * blockDim.x + threadIdx.x;
    if (i < n) dst[i] = src[i];
}
__global__ void zero_kernel(float* p, int n) {
    int i = blockIdx.x * 256 + threadIdx.x;
    if (i < n) p[i] = 0.f;
}

// weight col-max: W[l][K][N] -> ws[l][N] via atomicMax over 256-k strips
__global__ void wcolmax_kernel(const float* __restrict__ W, float* __restrict__ ws,
                               int K, int N) {
    int l = blockIdx.z;
    int n = blockIdx.x * 256 + threadIdx.x;
    int kbase = blockIdx.y * 256;
    const float* p = W + (size_t)l * K * N + (size_t)kbase * N + n;
    float m = 0.f;
    for (int k = 0; k < 256; k++) m = fmaxf(m, fabsf(p[(size_t)k * N]));
    atomicMax((unsigned*)&ws[(size_t)l * N + n], __float_as_uint(m));
}

// weight transpose-quantize: W[l][K][N] fp32 -> Q1,Q2 [l][N][K] int8
__global__ void wquant_kernel(const float* __restrict__ W, const float* __restrict__ ws,
                              int8_t* __restrict__ Q1, int8_t* __restrict__ Q2,
                              int K, int N) {
    __shared__ float t[32][33];
    int l = blockIdx.z;
    const float* Wl = W + (size_t)l * K * N;
    int n0 = blockIdx.x * 32, k0 = blockIdx.y * 32;
    #pragma unroll
    for (int r2 = 0; r2 < 4; r2++) {
        int k = threadIdx.y + r2 * 8;
        t[k][threadIdx.x] = Wl[(size_t)(k0 + k) * N + n0 + threadIdx.x];
    }
    __syncthreads();
    #pragma unroll
    for (int r2 = 0; r2 < 4; r2++) {
        int nl = threadIdx.y + r2 * 8;
        float sn = fmaxf(ws[(size_t)l * N + n0 + nl], 1e-20f);
        float xv = t[threadIdx.x][nl] * (127.0f / sn);
        int8_t d1, d2; q2digit(xv, d1, d2);
        size_t idx = (size_t)l * N * K + (size_t)(n0 + nl) * K + k0 + threadIdx.x;
        Q1[idx] = d1; Q2[idx] = d2;
    }
}

// row quantize: x fp32 [rows][ncols=2^shift] with row scales -> digits
__global__ void quantrows_kernel(const float* __restrict__ x, const float* __restrict__ rs,
                                 int8_t* __restrict__ q1, int8_t* __restrict__ q2,
                                 int n4, int shift) {
    int i = blockIdx.x * blockDim.x + threadIdx.x;
    if (i >= n4) return;
    int row = (i << 2) >> shift;
    float inv = 127.0f / fmaxf(rs[row], 1e-20f);
    float4 v = ((const float4*)x)[i];
    char4 c1, c2;
    { int8_t a, b2; q2digit(v.x * inv, a, b2); c1.x = a; c2.x = b2; }
    { int8_t a, b2; q2digit(v.y * inv, a, b2); c1.y = a; c2.y = b2; }
    { int8_t a, b2; q2digit(v.z * inv, a, b2); c1.z = a; c2.z = b2; }
    { int8_t a, b2; q2digit(v.w * inv, a, b2); c1.w = a; c2.w = b2; }
    ((char4*)q1)[i] = c1; ((char4*)q2)[i] = c2;
}

// ---------------- layernorm -> int8 digits + row scale ------------------------
__global__ __launch_bounds__(256) void lnq_kernel(
    const float* __restrict__ in, const float* __restrict__ w,
    const float* __restrict__ b, int8_t* __restrict__ q1,
    int8_t* __restrict__ q2, float* __restrict__ rs)
{
    int row = blockIdx.x;
    const float* x = in + (size_t)row * Dc;
    __shared__ float r1[8], r2[8];
    int wid = threadIdx.x >> 5, lane = threadIdx.x & 31;
    float xv[4];
    float s = 0.f, s2 = 0.f;
    #pragma unroll
    for (int j = 0; j < 4; j++) {
        xv[j] = x[threadIdx.x + j * 256];
        s += xv[j]; s2 += xv[j] * xv[j];
    }
    s = warp_sum(s); s2 = warp_sum(s2);
    if (lane == 0) { r1[wid] = s; r2[wid] = s2; }
    __syncthreads();
    if (wid == 0) {
        s  = (lane < 8) ? r1[lane] : 0.f;
        s2 = (lane < 8) ? r2[lane] : 0.f;
        s = warp_sum(s); s2 = warp_sum(s2);
        if (lane == 0) { r1[0] = s; r2[0] = s2; }
    }
    __syncthreads();
    float mean = r1[0] * (1.0f / Dc);
    float var  = r2[0] * (1.0f / Dc) - mean * mean;
    float inv  = rsqrtf(var + LN_EPS);
    float vv[4], am = 0.f;
    #pragma unroll
    for (int j = 0; j < 4; j++) {
        int i = threadIdx.x + j * 256;
        vv[j] = (xv[j] - mean) * inv * w[i] + b[i];
        am = fmaxf(am, fabsf(vv[j]));
    }
    __syncthreads();
    am = warp_max(am);
    if (lane == 0) r1[wid] = am;
    __syncthreads();
    if (wid == 0) {
        am = (lane < 8) ? r1[lane] : 0.f;
        am = warp_max(am);
        if (lane == 0) r1[0] = am;
    }
    __syncthreads();
    float sm = fmaxf(r1[0], 1e-20f);
    if (threadIdx.x == 0) rs[row] = sm;
    float qinv = 127.0f / sm;
    #pragma unroll
    for (int j = 0; j < 4; j++) {
        int i = threadIdx.x + j * 256;
        int8_t d1, d2; q2digit(vv[j] * qinv, d1, d2);
        q1[(size_t)row * Dc + i] = d1;
        q2[(size_t)row * Dc + i] = d2;
    }
}

// final layernorm (fp32 out)
__global__ __launch_bounds__(256) void lnf_kernel(
    const float* __restrict__ in, const float* __restrict__ w,
    const float* __restrict__ b, float* __restrict__ outf)
{
    int row = blockIdx.x;
    const float* x = in + (size_t)row * Dc;
    float s = 0.f, s2 = 0.f;
    for (int i = threadIdx.x; i < Dc; i += 256) {
        float v = x[i]; s += v; s2 += v * v;
    }
    __shared__ float r1[8], r2[8];
    s = warp_sum(s); s2 = warp_sum(s2);
    int wid = threadIdx.x >> 5, lane = threadIdx.x & 31;
    if (lane == 0) { r1[wid] = s; r2[wid] = s2; }
    __syncthreads();
    if (wid == 0) {
        s  = (lane < 8) ? r1[lane] : 0.f;
        s2 = (lane < 8) ? r2[lane] : 0.f;
        s = warp_sum(s); s2 = warp_sum(s2);
        if (lane == 0) { r1[0] = s; r2[0] = s2; }
    }
    __syncthreads();
    float mean = r1[0] * (1.0f / Dc);
    float var  = r2[0] * (1.0f / Dc) - mean * mean;
    float inv  = rsqrtf(var + LN_EPS);
    for (int i = threadIdx.x; i < Dc; i += 256)
        outf[(size_t)row * Dc + i] = (x[i] - mean) * inv * w[i] + b[i];
}

// ---------------- INT8 dual-digit tensor-core GEMM ----------------------------
// C = (sa_i*sb_j/16129)*(S1 + S2/254) + bias, S1=a1b1, S2=a1b2+a2b1 (s32 exact)
// EPI 1: Cf = res + v ; EPI 3: v -> bf16 hi/lo (qkv) ; EPI 4: relu -> fp32 + rowmax
#define KB 64                       // K-bytes per stage (2 IMMA k-steps)
#define RSTR 80                     // padded row stride (64 + 16)
#define TILEB (128*RSTR)            // 10240 B per (buf,dig) tile
#define GSMEM (8*TILEB)             // 81920 B: A[2buf][2dig] + B[2buf][2dig]

template<int EPI>
__global__ void __launch_bounds__(256) gemm_i8(
    const int8_t* __restrict__ Aq1, const int8_t* __restrict__ Aq2,
    const float* __restrict__ sa,
    const int8_t* __restrict__ Bq1, const int8_t* __restrict__ Bq2,
    const float* __restrict__ sb,
    const float* __restrict__ bias, const float* __restrict__ res,
    float* __restrict__ Cf, bf16* __restrict__ Chi, bf16* __restrict__ Clo,
    float* __restrict__ rowmax,
    int M, int N, int K)
{
    extern __shared__ __align__(16) char smem[];
    const int tid = threadIdx.x, lane = tid & 31, wid = tid >> 5;
    const int wm = wid & 3, wn = wid >> 2;
    const int bm = blockIdx.y * 128, bn = blockIdx.x * 128;
    const unsigned sb0 = smem_u32(smem);

    int s1[2][8][4] = {}; int s2[2][8][4] = {};

    auto fill = [&](int it, int buf) {
        int k0 = it * KB;
        #pragma unroll
        for (int j = 0; j < 4; j++) {            // A: 1024 chunks
            int c = tid + j * 256;
            int dig = c >> 9, rem = c & 511, row = rem >> 2, half = rem & 3;
            const int8_t* src = (dig ? Aq2 : Aq1) + (size_t)(bm + row) * K + k0 + half * 16;
            cp_async16(sb0 + (buf*2 + dig) * TILEB + row * RSTR + half * 16, src);
        }
        #pragma unroll
        for (int j = 0; j < 4; j++) {            // B: 1024 chunks
            int c = tid + j * 256;
            int dig = c >> 9, rem = c & 511, row = rem >> 2, half = rem & 3;
            const int8_t* src = (dig ? Bq2 : Bq1) + (size_t)(bn + row) * K + k0 + half * 16;
            cp_async16(sb0 + (4 + buf*2 + dig) * TILEB + row * RSTR + half * 16, src);
        }
        asm volatile("cp.async.commit_group;" ::: "memory");
    };

    fill(0, 0);
    const int NIT = K / KB;
    const int kn_l = (lane & 7) + ((lane >> 4) << 3);
    const unsigned aoff = (unsigned)((wm * 32 + (lane & 15)) * RSTR + ((lane >> 4) << 4));
    const unsigned bhalf = ((unsigned)((lane >> 3) & 1)) << 4;

    for (int it = 0; it < NIT; it++) {
        int buf = it & 1;
        if (it + 1 < NIT) {
            fill(it + 1, buf ^ 1);
            asm volatile("cp.async.wait_group 1;" ::: "memory");
        } else {
            asm volatile("cp.async.wait_group 0;" ::: "memory");
        }
        __syncthreads();
        #pragma unroll
        for (int ks = 0; ks < 2; ks++) {
            unsigned kbyte = (unsigned)(ks * 32);
            unsigned a1f[2][4], a2f[2][4];
            #pragma unroll
            for (int mt = 0; mt < 2; mt++) {
                ldsm4(a1f[mt], sb0 + (buf*2 + 0)*TILEB + aoff + mt*16*RSTR + kbyte);
                ldsm4(a2f[mt], sb0 + (buf*2 + 1)*TILEB + aoff + mt*16*RSTR + kbyte);
            }
            #pragma unroll
            for (int np = 0; np < 4; np++) {
                unsigned off = (unsigned)((wn*64 + np*16 + kn_l) * RSTR) + bhalf + kbyte;
                unsigned r1[4], r2[4];
                ldsm4(r1, sb0 + (4 + buf*2 + 0)*TILEB + off);
                ldsm4(r2, sb0 + (4 + buf*2 + 1)*TILEB + off);
                #pragma unroll
                for (int h = 0; h < 2; h++) {
                    int nt = 2*np + h;
                    unsigned b1[2] = {r1[2*h], r1[2*h+1]};
                    unsigned b2[2] = {r2[2*h], r2[2*h+1]};
                    #pragma unroll
                    for (int mt = 0; mt < 2; mt++) {
                        imma(s1[mt][nt], a1f[mt], b1);
                        imma(s2[mt][nt], a1f[mt], b2);
                        imma(s2[mt][nt], a2f[mt], b1);
                    }
                }
            }
        }
        __syncthreads();
    }

    // epilogue
    #pragma unroll
    for (int mt = 0; mt < 2; mt++) {
        #pragma unroll
        for (int hh = 0; hh < 2; hh++) {
            int rr = bm + wm*32 + mt*16 + (lane >> 2) + hh*8;
            float sav = __ldg(&sa[rr]) * (1.0f / 16129.0f);
            float rmax = 0.f;
            #pragma unroll
            for (int nt = 0; nt < 8; nt++) {
                #pragma unroll
                for (int cc = 0; cc < 2; cc++) {
                    int col = bn + wn*64 + nt*8 + ((lane & 3) << 1) + cc;
                    float v = sav * __ldg(&sb[col]) *
                              ((float)s1[mt][nt][hh*2+cc] + (float)s2[mt][nt][hh*2+cc] * (1.0f/254.0f))
                              + __ldg(&bias[col]);
                    size_t idx = (size_t)rr * N + col;
                    if (EPI == 1) {
                        Cf[idx] = res[idx] + v;
                    } else if (EPI == 3) {
                        bf16 vh, vl; split2(v, vh, vl);
                        Chi[idx] = vh; Clo[idx] = vl;
                    } else {
                        v = fmaxf(v, 0.f);
                        Cf[idx] = v;
                        rmax = fmaxf(rmax, v);
                    }
                }
            }
            if (EPI == 4) {
                rmax = fmaxf(rmax, __shfl_xor_sync(0xffffffffu, rmax, 1));
                rmax = fmaxf(rmax, __shfl_xor_sync(0xffffffffu, rmax, 2));
                if ((lane & 3) == 0)
                    atomicMax((unsigned*)&rowmax[rr], __float_as_uint(rmax));
            }
        }
    }
}

// ---------------- HMMA flash attention (bf16x3) -------------------------------
#define AQ 128
#define AKT 64
#define QSTR 72
#define ASMEM_BYTES (2*128*QSTR*2 + 4*64*QSTR*2 + 256)

__global__ void __launch_bounds__(256, 1) attn_mma_kernel(
    const bf16* __restrict__ qkv_hi, const bf16* __restrict__ qkv_lo,
    const float* __restrict__ amask,
    float* __restrict__ ctx, float* __restrict__ cs)
{
    extern __shared__ __align__(16) char asmem[];
    bf16* sQh = (bf16*)asmem;
    bf16* sQl = sQh + 128*QSTR;
    bf16* sKh = sQl + 128*QSTR;
    bf16* sKl = sKh + 64*QSTR;
    bf16* sVh = sKl + 64*QSTR;
    bf16* sVl = sVh + 64*QSTR;
    float* skm = (float*)(sVl + 64*QSTR);

    const int tid = threadIdx.x, lane = tid & 31, w = tid >> 5;
    const int bh = blockIdx.y, b = bh >> 4, hh = bh & 15;
    const int q0 = blockIdx.x * AQ;
    const float scale = 0.125f;

    const size_t rstr = 3 * Dc;
    const bf16* qh = qkv_hi + (size_t)b * Tc * rstr + hh * HD;
    const bf16* ql = qkv_lo + (size_t)b * Tc * rstr + hh * HD;
    const bf16* kh = qh + Dc;  const bf16* kl = ql + Dc;
    const bf16* vh = qh + 2*Dc; const bf16* vl = ql + 2*Dc;

    #pragma unroll
    for (int j = 0; j < 8; j++) {
        int c = tid + j * 256;
        int p = c >> 10, rem = c & 1023;
        int row = rem >> 3, ch = rem & 7;
        *(uint4*)((p ? sQl : sQh) + row * QSTR + ch * 8) =
            *(const uint4*)((p ? ql : qh) + (size_t)(q0 + row) * rstr + ch * 8);
    }
    __syncthreads();

    const unsigned qb_h = smem_u32(sQh), qb_l = smem_u32(sQl);
    const unsigned kb_h = smem_u32(sKh), kb_l = smem_u32(sKl);
    const unsigned vb_h = smem_u32(sVh), vb_l = smem_u32(sVl);

    unsigned aQh[4][4], aQl[4][4];
    {
        int arow = w * 16 + (lane & 15);
        #pragma unroll
        for (int g = 0; g < 4; g++) {
            int acol = g * 16 + ((lane >> 4) << 3);
            unsigned off = (unsigned)(arow * QSTR + acol) * 2u;
            ldsm4(aQh[g], qb_h + off);
            ldsm4(aQl[g], qb_l + off);
        }
    }

    float acc[8][4];
    #pragma unroll
    for (int nt = 0; nt < 8; nt++)
        #pragma unroll
        for (int e = 0; e < 4; e++) acc[nt][e] = 0.f;
    float m0 = -1e30f, m1 = -1e30f, l0 = 0.f, l1 = 0.f;

    const int qg0 = q0 + w * 16 + (lane >> 2);
    const int ncol = (lane & 3) << 1;
    const int kn_l = (lane & 7) + ((lane >> 4) << 3);
    const int kkoff = ((lane >> 3) & 1) << 3;

    const int nkt = 2 * blockIdx.x + 2;
    for (int kt = 0; kt < nkt; kt++) {
        int kk0 = kt * AKT;
        __syncthreads();
        #pragma unroll
        for (int j = 0; j < 8; j++) {
            int c = tid + j * 256;
            int arr = c >> 9, rem = c & 511;
            int row = rem >> 3, ch = rem & 7;
            const bf16* gp = (arr == 0) ? kh : (arr == 1) ? kl : (arr == 2) ? vh : vl;
            bf16* sp = (arr == 0) ? sKh : (arr == 1) ? sKl : (arr == 2) ? sVh : sVl;
            *(uint4*)(sp + row * QSTR + ch * 8) =
                *(const uint4*)(gp + (size_t)(kk0 + row) * rstr + ch * 8);
        }
        if (tid < 64) skm[tid] = (1.0f - amask[b * Tc + kk0 + tid]) * MASK_BIAS;
        __syncthreads();

        float S[8][4];
        #pragma unroll
        for (int nt = 0; nt < 8; nt++)
            #pragma unroll
            for (int e = 0; e < 4; e++) S[nt][e] = 0.f;

        #pragma unroll
        for (int g = 0; g < 4; g++) {
            unsigned bKh[8][2], bKl[8][2];
            #pragma unroll
            for (int np = 0; np < 4; np++) {
                unsigned off = (unsigned)((np * 16 + kn_l) * QSTR + g * 16 + kkoff) * 2u;
                unsigned r4[4];
                ldsm4(r4, kb_h + off);
                bKh[2*np][0] = r4[0]; bKh[2*np][1] = r4[1];
                bKh[2*np+1][0] = r4[2]; bKh[2*np+1][1] = r4[3];
                ldsm4(r4, kb_l + off);
                bKl[2*np][0] = r4[0]; bKl[2*np][1] = r4[1];
                bKl[2*np+1][0] = r4[2]; bKl[2*np+1][1] = r4[3];
            }
            #pragma unroll
            for (int nt = 0; nt < 8; nt++) {
                mma16816(S[nt], aQh[g], bKh[nt]);
                mma16816(S[nt], aQh[g], bKl[nt]);
                mma16816(S[nt], aQl[g], bKh[nt]);
            }
        }

        float tmax0 = -1e30f, tmax1 = -1e30f;
        #pragma unroll
        for (int nt = 0; nt < 8; nt++) {
            int n0 = kk0 + nt * 8 + ncol;
            float km0 = skm[nt * 8 + ncol], km1 = skm[nt * 8 + ncol + 1];
            float s0 = (n0     <= qg0    ) ? S[nt][0] * scale + km0 : -1e30f;
            float s1v = (n0 + 1 <= qg0   ) ? S[nt][1] * scale + km1 : -1e30f;
            float s2v = (n0     <= qg0+8 ) ? S[nt][2] * scale + km0 : -1e30f;
            float s3 = (n0 + 1 <= qg0+8  ) ? S[nt][3] * scale + km1 : -1e30f;
            S[nt][0] = s0; S[nt][1] = s1v; S[nt][2] = s2v; S[nt][3] = s3;
            tmax0 = fmaxf(tmax0, fmaxf(s0, s1v));
            tmax1 = fmaxf(tmax1, fmaxf(s2v, s3));
        }
        tmax0 = fmaxf(tmax0, __shfl_xor_sync(0xffffffffu, tmax0, 1));
        tmax0 = fmaxf(tmax0, __shfl_xor_sync(0xffffffffu, tmax0, 2));
        tmax1 = fmaxf(tmax1, __shfl_xor_sync(0xffffffffu, tmax1, 1));
        tmax1 = fmaxf(tmax1, __shfl_xor_sync(0xffffffffu, tmax1, 2));

        float nm0 = fmaxf(m0, tmax0), nm1 = fmaxf(m1, tmax1);
        float cr0 = __expf(m0 - nm0), cr1 = __expf(m1 - nm1);
        m0 = nm0; m1 = nm1;

        float sum0 = 0.f, sum1 = 0.f;
        #pragma unroll
        for (int nt = 0; nt < 8; nt++) {
            float p0 = __expf(S[nt][0] - m0);
            float p1 = __expf(S[nt][1] - m0);
            float p2 = __expf(S[nt][2] - m1);
            float p3 = __expf(S[nt][3] - m1);
            S[nt][0] = p0; S[nt][1] = p1; S[nt][2] = p2; S[nt][3] = p3;
            sum0 += p0 + p1; sum1 += p2 + p3;
        }
        sum0 += __shfl_xor_sync(0xffffffffu, sum0, 1);
        sum0 += __shfl_xor_sync(0xffffffffu, sum0, 2);
        sum1 += __shfl_xor_sync(0xffffffffu, sum1, 1);
        sum1 += __shfl_xor_sync(0xffffffffu, sum1, 2);
        l0 = l0 * cr0 + sum0;
        l1 = l1 * cr1 + sum1;
        #pragma unroll
        for (int nt = 0; nt < 8; nt++) {
            acc[nt][0] *= cr0; acc[nt][1] *= cr0;
            acc[nt][2] *= cr1; acc[nt][3] *= cr1;
        }

        #pragma unroll
        for (int g = 0; g < 4; g++) {
            unsigned aPh[4], aPl[4];
            packsplit(S[2*g][0],   S[2*g][1],   aPh[0], aPl[0]);
            packsplit(S[2*g][2],   S[2*g][3],   aPh[1], aPl[1]);
            packsplit(S[2*g+1][0], S[2*g+1][1], aPh[2], aPl[2]);
            packsplit(S[2*g+1][2], S[2*g+1][3], aPh[3], aPl[3]);
            unsigned bVh[8][2], bVl[8][2];
            int brow = g * 16 + (lane & 15);
            #pragma unroll
            for (int np = 0; np < 4; np++) {
                int bcol = np * 16 + ((lane >> 4) << 3);
                unsigned off = (unsigned)(brow * QSTR + bcol) * 2u;
                unsigned r4[4];
                ldsm4t(r4, vb_h + off);
                bVh[2*np][0] = r4[0]; bVh[2*np][1] = r4[1];
                bVh[2*np+1][0] = r4[2]; bVh[2*np+1][1] = r4[3];
                ldsm4t(r4, vb_l + off);
                bVl[2*np][0] = r4[0]; bVl[2*np][1] = r4[1];
                bVl[2*np+1][0] = r4[2]; bVl[2*np+1][1] = r4[3];
            }
            #pragma unroll
            for (int nt = 0; nt < 8; nt++) {
                mma16816(acc[nt], aPh, bVh[nt]);
                mma16816(acc[nt], aPh, bVl[nt]);
                mma16816(acc[nt], aPl, bVh[nt]);
            }
        }
    }

    // epilogue: ctx fp32 + per-row absmax via deterministic atomicMax
    float il0 = 1.0f / l0, il1 = 1.0f / l1;
    int row0 = q0 + w * 16 + (lane >> 2);
    int gr0 = b * Tc + row0, gr1 = gr0 + 8;
    size_t o0 = (size_t)gr0 * Dc + hh * HD + ncol;
    size_t o1 = (size_t)gr1 * Dc + hh * HD + ncol;
    float mx0 = 0.f, mx1 = 0.f;
    #pragma unroll
    for (int nt = 0; nt < 8; nt++) {
        float v0 = acc[nt][0] * il0, v1 = acc[nt][1] * il0;
        float v2 = acc[nt][2] * il1, v3 = acc[nt][3] * il1;
        *(float2*)(ctx + o0 + nt*8) = make_float2(v0, v1);
        *(float2*)(ctx + o1 + nt*8) = make_float2(v2, v3);
        mx0 = fmaxf(mx0, fmaxf(fabsf(v0), fabsf(v1)));
        mx1 = fmaxf(mx1, fmaxf(fabsf(v2), fabsf(v3)));
    }
    mx0 = fmaxf(mx0, __shfl_xor_sync(0xffffffffu, mx0, 1));
    mx0 = fmaxf(mx0, __shfl_xor_sync(0xffffffffu, mx0, 2));
    mx1 = fmaxf(mx1, __shfl_xor_sync(0xffffffffu, mx1, 1));
    mx1 = fmaxf(mx1, __shfl_xor_sync(0xffffffffu, mx1, 2));
    if ((lane & 3) == 0) {
        atomicMax((unsigned*)&cs[gr0], __float_as_uint(mx0));
        atomicMax((unsigned*)&cs[gr1], __float_as_uint(mx1));
    }
}

// ---------------- launch -----------------------------------------------------
extern "C" void kernel_launch(void* const* d_in, const int* in_sizes, int n_in,
                              void* d_out, int out_size)
{
    const float* emb    = (const float*)d_in[0];
    const float* amask  = (const float*)d_in[1];
    const float* ln1_w  = (const float*)d_in[2];
    const float* ln1_b  = (const float*)d_in[3];
    const float* attn_w = (const float*)d_in[4];
    const float* attn_b = (const float*)d_in[5];
    const float* proj_w = (const float*)d_in[6];
    const float* proj_b = (const float*)d_in[7];
    const float* ln2_w  = (const float*)d_in[8];
    const float* ln2_b  = (const float*)d_in[9];
    const float* fc_w   = (const float*)d_in[10];
    const float* fc_b   = (const float*)d_in[11];
    const float* fcp_w  = (const float*)d_in[12];
    const float* fcp_b  = (const float*)d_in[13];
    const float* lnf_w  = (const float*)d_in[14];
    const float* lnf_b  = (const float*)d_in[15];
    float* out = (float*)d_out;

    float *h, *ctx, *act, *xs, *cs, *as_, *wqs, *wps, *wfs, *wgs;
    bf16 *qhi, *qlo;
    int8_t *xq1,*xq2,*cq1,*cq2,*aq1,*aq2;
    int8_t *wq1,*wq2,*wp1,*wp2,*wf1,*wf2,*wg1,*wg2;
    cudaGetSymbolAddress((void**)&h,   g_h);
    cudaGetSymbolAddress((void**)&ctx, g_ctx);
    cudaGetSymbolAddress((void**)&act, g_act);
    cudaGetSymbolAddress((void**)&qhi, g_qhi); cudaGetSymbolAddress((void**)&qlo, g_qlo);
    cudaGetSymbolAddress((void**)&xq1, g_xq1); cudaGetSymbolAddress((void**)&xq2, g_xq2);
    cudaGetSymbolAddress((void**)&cq1, g_cq1); cudaGetSymbolAddress((void**)&cq2, g_cq2);
    cudaGetSymbolAddress((void**)&aq1, g_aq1); cudaGetSymbolAddress((void**)&aq2, g_aq2);
    cudaGetSymbolAddress((void**)&xs,  g_xs);  cudaGetSymbolAddress((void**)&cs, g_cs);
    cudaGetSymbolAddress((void**)&as_, g_as);
    cudaGetSymbolAddress((void**)&wq1, g_wq1); cudaGetSymbolAddress((void**)&wq2, g_wq2);
    cudaGetSymbolAddress((void**)&wp1, g_wp1); cudaGetSymbolAddress((void**)&wp2, g_wp2);
    cudaGetSymbolAddress((void**)&wf1, g_wf1); cudaGetSymbolAddress((void**)&wf2, g_wf2);
    cudaGetSymbolAddress((void**)&wg1, g_wg1); cudaGetSymbolAddress((void**)&wg2, g_wg2);
    cudaGetSymbolAddress((void**)&wqs, g_wqs); cudaGetSymbolAddress((void**)&wps, g_wps);
    cudaGetSymbolAddress((void**)&wfs, g_wfs); cudaGetSymbolAddress((void**)&wgs, g_wgs);

    cudaFuncSetAttribute(gemm_i8<1>, cudaFuncAttributeMaxDynamicSharedMemorySize, GSMEM);
    cudaFuncSetAttribute(gemm_i8<3>, cudaFuncAttributeMaxDynamicSharedMemorySize, GSMEM);
    cudaFuncSetAttribute(gemm_i8<4>, cudaFuncAttributeMaxDynamicSharedMemorySize, GSMEM);
    cudaFuncSetAttribute(attn_mma_kernel, cudaFuncAttributeMaxDynamicSharedMemorySize, ASMEM_BYTES);

    // weight quantization (per replay)
    zero_kernel<<<(Lc*3*Dc+255)/256, 256>>>(wqs, Lc*3*Dc);
    zero_kernel<<<(Lc*Dc+255)/256, 256>>>(wps, Lc*Dc);
    zero_kernel<<<(Lc*Ic+255)/256, 256>>>(wfs, Lc*Ic);
    zero_kernel<<<(Lc*Dc+255)/256, 256>>>(wgs, Lc*Dc);
    wcolmax_kernel<<<dim3(3*Dc/256, Dc/256, Lc), 256>>>(attn_w, wqs, Dc, 3*Dc);
    wcolmax_kernel<<<dim3(Dc/256,   Dc/256, Lc), 256>>>(proj_w, wps, Dc, Dc);
    wcolmax_kernel<<<dim3(Ic/256,   Dc/256, Lc), 256>>>(fc_w,   wfs, Dc, Ic);
    wcolmax_kernel<<<dim3(Dc/256,   Ic/256, Lc), 256>>>(fcp_w,  wgs, Ic, Dc);
    wquant_kernel<<<dim3(3*Dc/32, Dc/32, Lc), dim3(32,8)>>>(attn_w, wqs, wq1, wq2, Dc, 3*Dc);
    wquant_kernel<<<dim3(Dc/32,   Dc/32, Lc), dim3(32,8)>>>(proj_w, wps, wp1, wp2, Dc, Dc);
    wquant_kernel<<<dim3(Ic/32,   Dc/32, Lc), dim3(32,8)>>>(fc_w,   wfs, wf1, wf2, Dc, Ic);
    wquant_kernel<<<dim3(Dc/32,   Ic/32, Lc), dim3(32,8)>>>(fcp_w,  wgs, wg1, wg2, Ic, Dc);

    { int n = ROWS * Dc; copy_kernel<<<(n + 255) / 256, 256>>>(emb, h, n); }

    for (int l = 0; l < Lc; l++) {
        zero_kernel<<<(ROWS+255)/256, 256>>>(cs, ROWS);
        zero_kernel<<<(ROWS+255)/256, 256>>>(as_, ROWS);
        // x = ln1(h) -> int8 digits
        lnq_kernel<<<ROWS, 256>>>(h, ln1_w + (size_t)l*Dc, ln1_b + (size_t)l*Dc, xq1, xq2, xs);
        // qkv = x @ attn_w + b -> bf16 hi/lo
        gemm_i8<3><<<dim3(3*Dc/128, ROWS/128), 256, GSMEM>>>(
            xq1, xq2, xs, wq1 + (size_t)l*3*Dc*Dc, wq2 + (size_t)l*3*Dc*Dc, wqs + (size_t)l*3*Dc,
            attn_b + (size_t)l*3*Dc, nullptr, nullptr, qhi, qlo, nullptr, ROWS, 3*Dc, Dc);
        // attention -> ctx fp32 + rowmax
        attn_mma_kernel<<<dim3(Tc/AQ, Bc*Hc), 256, ASMEM_BYTES>>>(qhi, qlo, amask, ctx, cs);
        quantrows_kernel<<<(ROWS*Dc/4 + 255)/256, 256>>>(ctx, cs, cq1, cq2, ROWS*Dc/4, 10);
        // h += ctx @ proj_w + b
        gemm_i8<1><<<dim3(Dc/128, ROWS/128), 256, GSMEM>>>(
            cq1, cq2, cs, wp1 + (size_t)l*Dc*Dc, wp2 + (size_t)l*Dc*Dc, wps + (size_t)l*Dc,
            proj_b + (size_t)l*Dc, h, h, nullptr, nullptr, nullptr, ROWS, Dc, Dc);
        // x = ln2(h) -> int8 digits
        lnq_kernel<<<ROWS, 256>>>(h, ln2_w + (size_t)l*Dc, ln2_b + (size_t)l*Dc, xq1, xq2, xs);
        // act = relu(x @ fc_w + b) -> fp32 + rowmax
        gemm_i8<4><<<dim3(Ic/128, ROWS/128), 256, GSMEM>>>(
            xq1, xq2, xs, wf1 + (size_t)l*Ic*Dc, wf2 + (size_t)l*Ic*Dc, wfs + (size_t)l*Ic,
            fc_b + (size_t)l*Ic, nullptr, act, nullptr, nullptr, as_, ROWS, Ic, Dc);
        quantrows_kernel<<<(ROWS*Ic/4 + 255)/256, 256>>>(act, as_, aq1, aq2, ROWS*Ic/4, 12);
        // h += act @ fcp_w + b
        gemm_i8<1><<<dim3(Dc/128, ROWS/128), 256, GSMEM>>>(
            aq1, aq2, as_, wg1 + (size_t)l*Dc*Ic, wg2 + (size_t)l*Dc*Ic, wgs + (size_t)l*Dc,
            fcp_b + (size_t)l*Dc, h, h, nullptr, nullptr, nullptr, ROWS, Dc, Ic);
    }
    lnf_kernel<<<ROWS, 256>>>(h, lnf_w, lnf_b, out);
}

// round 13
// speedup vs baseline: 2.3466x; 2.3466x over previous
#include <cuda_runtime.h>
#include <cuda_bf16.h>
#include <math.h>
#include <stdint.h>

// Problem constants
#define Bc 2
#define Tc 2048
#define Dc 1024
#define Hc 16
#define Lc 8
#define Ic 4096
#define HD 64
#define ROWS (Bc*Tc)    // 4096 token rows
#define LN_EPS 1e-5f
#define MASK_BIAS -10000.0f

typedef __nv_bfloat16 bf16;

// ---------------- scratch (static device globals; no allocation) -------------
__device__ float g_h[ROWS * Dc];            // residual stream (fp32)
__device__ bf16  g_qhi[ROWS * 3 * Dc], g_qlo[ROWS * 3 * Dc];  // qkv split
__device__ bf16  g_xhi[ROWS * Dc],  g_xlo[ROWS * Dc];     // LN output split
__device__ bf16  g_chi[ROWS * Dc],  g_clo[ROWS * Dc];     // attention ctx split
__device__ bf16  g_ahi[ROWS * Ic],  g_alo[ROWS * Ic];     // ffn inner split
// weight splits [K, N] layout
__device__ bf16 g_wqkv_hi[Lc*Dc*3*Dc], g_wqkv_lo[Lc*Dc*3*Dc];
__device__ bf16 g_wprj_hi[Lc*Dc*Dc],   g_wprj_lo[Lc*Dc*Dc];
__device__ bf16 g_wfc_hi [Lc*Dc*Ic],   g_wfc_lo [Lc*Dc*Ic];
__device__ bf16 g_wfp_hi [Lc*Ic*Dc],   g_wfp_lo [Lc*Ic*Dc];

// ---------------- utility ----------------------------------------------------
__inline__ __device__ float warp_sum(float v) {
    #pragma unroll
    for (int o = 16; o > 0; o >>= 1) v += __shfl_xor_sync(0xffffffffu, v, o);
    return v;
}
__device__ __forceinline__ void split2(float v, bf16& hi, bf16& lo) {
    hi = __float2bfloat16(v);
    lo = __float2bfloat16(v - __bfloat162float(hi));
}

// ---------------- weight split ------------------------------------------------
__global__ void split4_kernel(const float* __restrict__ src,
                              bf16* __restrict__ hi, bf16* __restrict__ lo, int n4) {
    int i = blockIdx.x * blockDim.x + threadIdx.x;
    if (i >= n4) return;
    float4 v = ((const float4*)src)[i];
    bf16 h0,l0,h1,l1,h2,l2,h3,l3;
    split2(v.x,h0,l0); split2(v.y,h1,l1); split2(v.z,h2,l2); split2(v.w,h3,l3);
    __nv_bfloat162* H = (__nv_bfloat162*)(hi + 4*(size_t)i);
    __nv_bfloat162* L = (__nv_bfloat162*)(lo + 4*(size_t)i);
    H[0] = __nv_bfloat162(h0,h1); H[1] = __nv_bfloat162(h2,h3);
    L[0] = __nv_bfloat162(l0,l1); L[1] = __nv_bfloat162(l2,l3);
}

// ---------------- layernorm (float4 vectorized) -------------------------------
template<bool SPLIT>
__global__ __launch_bounds__(256) void ln_kernel(
    const float* __restrict__ in, const float* __restrict__ w,
    const float* __restrict__ b, float* __restrict__ outf,
    bf16* __restrict__ outhi, bf16* __restrict__ outlo)
{
    int row = blockIdx.x;
    const float4* x4 = (const float4*)(in + (size_t)row * Dc);
    float4 xv = x4[threadIdx.x];
    float s  = xv.x + xv.y + xv.z + xv.w;
    float s2 = xv.x*xv.x + xv.y*xv.y + xv.z*xv.z + xv.w*xv.w;
    __shared__ float r1[8], r2[8];
    s = warp_sum(s); s2 = warp_sum(s2);
    int wid = threadIdx.x >> 5, lane = threadIdx.x & 31;
    if (lane == 0) { r1[wid] = s; r2[wid] = s2; }
    __syncthreads();
    if (wid == 0) {
        s  = (lane < 8) ? r1[lane] : 0.f;
        s2 = (lane < 8) ? r2[lane] : 0.f;
        s = warp_sum(s); s2 = warp_sum(s2);
        if (lane == 0) { r1[0] = s; r2[0] = s2; }
    }
    __syncthreads();
    float mean = r1[0] * (1.0f / Dc);
    float var  = r2[0] * (1.0f / Dc) - mean * mean;
    float inv  = rsqrtf(var + LN_EPS);
    float4 wv = ((const float4*)w)[threadIdx.x];
    float4 bv = ((const float4*)b)[threadIdx.x];
    float v0 = (xv.x - mean) * inv * wv.x + bv.x;
    float v1 = (xv.y - mean) * inv * wv.y + bv.y;
    float v2 = (xv.z - mean) * inv * wv.z + bv.z;
    float v3 = (xv.w - mean) * inv * wv.w + bv.w;
    if (SPLIT) {
        bf16 h0,l0,h1,l1,h2,l2,h3,l3;
        split2(v0,h0,l0); split2(v1,h1,l1); split2(v2,h2,l2); split2(v3,h3,l3);
        __nv_bfloat162 H[2] = {__nv_bfloat162(h0,h1), __nv_bfloat162(h2,h3)};
        __nv_bfloat162 L[2] = {__nv_bfloat162(l0,l1), __nv_bfloat162(l2,l3)};
        *(uint2*)(outhi + (size_t)row * Dc + threadIdx.x * 4) = *(uint2*)H;
        *(uint2*)(outlo + (size_t)row * Dc + threadIdx.x * 4) = *(uint2*)L;
    } else {
        ((float4*)(outf + (size_t)row * Dc))[threadIdx.x] = make_float4(v0, v1, v2, v3);
    }
}

// ---------------- MMA / ldmatrix helpers --------------------------------------
__device__ __forceinline__ void ldsm4(unsigned* r, unsigned addr) {
    asm volatile("ldmatrix.sync.aligned.m8n8.x4.shared.b16 {%0,%1,%2,%3},[%4];"
        : "=r"(r[0]), "=r"(r[1]), "=r"(r[2]), "=r"(r[3]) : "r"(addr));
}
__device__ __forceinline__ void ldsm4t(unsigned* r, unsigned addr) {
    asm volatile("ldmatrix.sync.aligned.m8n8.x4.trans.shared.b16 {%0,%1,%2,%3},[%4];"
        : "=r"(r[0]), "=r"(r[1]), "=r"(r[2]), "=r"(r[3]) : "r"(addr));
}
__device__ __forceinline__ void mma16816(float* c, const unsigned* a, const unsigned* b) {
    asm volatile("mma.sync.aligned.m16n8k16.row.col.f32.bf16.bf16.f32 "
        "{%0,%1,%2,%3},{%4,%5,%6,%7},{%8,%9},{%0,%1,%2,%3};"
        : "+f"(c[0]), "+f"(c[1]), "+f"(c[2]), "+f"(c[3])
        : "r"(a[0]), "r"(a[1]), "r"(a[2]), "r"(a[3]), "r"(b[0]), "r"(b[1]));
}
__device__ __forceinline__ void cp_async16(unsigned saddr, const void* g) {
    asm volatile("cp.async.cg.shared.global [%0], [%1], 16;" :: "r"(saddr), "l"(g));
}
__device__ __forceinline__ unsigned smem_u32(const void* p) {
    return (unsigned)__cvta_generic_to_shared(p);
}
__device__ __forceinline__ void packsplit(float x, float y, unsigned& hi, unsigned& lo) {
    bf16 hx = __float2bfloat16(x);
    bf16 hy = __float2bfloat16(y);
    bf16 lx = __float2bfloat16(x - __bfloat162float(hx));
    bf16 ly = __float2bfloat16(y - __bfloat162float(hy));
    __nv_bfloat162 H(hx, hy), L(lx, ly);
    hi = *(unsigned*)&H; lo = *(unsigned*)&L;
}

// ---------------- tensor-core GEMM (bf16x3, persistent tiles) ------------------
// EPI 0: Cf = v+bias ; 1: Cf = res+v+bias ; 2: relu(v+bias)->split ; 3: (v+bias)->split
#define GBM 128
#define GBN 128
#define GBK 32
#define APAD 8
#define ASTRIDE (GBK + APAD)          // 40 elems (80B rows)
#define SA_ELEMS (2*2*GBM*ASTRIDE)    // 40960 bf16 = 81920 B
#define SB_BYTES_TILE (GBK * 256)     // 8192 B per (buf,p) tile
#define SB_BYTES (2*2*SB_BYTES_TILE)  // 32768 B
#define GSMEM_BYTES (SA_ELEMS*2 + SB_BYTES)   // 114688 B
#define GPERS 296                      // 2 CTAs x 148 SMs

template<int EPI>
__global__ void __launch_bounds__(256, 2) gemm3_kernel(
    const bf16* __restrict__ Ahi, const bf16* __restrict__ Alo,
    const bf16* __restrict__ Bhi, const bf16* __restrict__ Blo,
    const float* __restrict__ bias, const float* __restrict__ res,
    float* __restrict__ Cf, bf16* __restrict__ Chi, bf16* __restrict__ Clo,
    int M, int N, int K)
{
    extern __shared__ __align__(16) bf16 smem[];
    bf16* sA = smem;
    char* sB = (char*)(smem + SA_ELEMS);
    const int tid = threadIdx.x;
    const int lane = tid & 31, wid = tid >> 5;
    const int wm = wid & 3, wn = wid >> 2;
    unsigned sA_base = smem_u32(sA);
    unsigned sB_base = smem_u32(sB);

    const int tilesN = N >> 7;
    const int ntiles = (M >> 7) * tilesN;
    const int NIT = K >> 5;

    for (int t = blockIdx.x; t < ntiles; t += gridDim.x) {
        const int bm = (t / tilesN) << 7;
        const int bn = (t % tilesN) << 7;

        float acc[2][8][4] = {};

        auto issue = [&](int it, int buf) {
            int k0 = it * GBK;
            #pragma unroll
            for (int j = 0; j < 4; j++) {
                int c = tid + j * 256;
                int p = c >> 9, rem = c & 511;
                int r = rem >> 2, kc = (rem & 3) << 3;
                const bf16* src = (p ? Alo : Ahi) + (size_t)(bm + r) * K + k0 + kc;
                unsigned dst = sA_base + (unsigned)(((buf*2 + p)*GBM + r)*ASTRIDE + kc) * 2u;
                cp_async16(dst, src);
            }
            #pragma unroll
            for (int j = 0; j < 4; j++) {
                int c = tid + j * 256;
                int p = c >> 9, rem = c & 511;
                int k = rem >> 4, nc = rem & 15;
                const bf16* src = (p ? Blo : Bhi) + (size_t)(k0 + k) * N + bn + nc * 8;
                unsigned dst = sB_base + (unsigned)((buf*2 + p) * SB_BYTES_TILE
                              + k * 256 + ((nc ^ (k & 7)) << 4));
                cp_async16(dst, src);
            }
            asm volatile("cp.async.commit_group;" ::: "memory");
        };

        issue(0, 0);
        for (int it = 0; it < NIT; it++) {
            int buf = it & 1;
            if (it + 1 < NIT) {
                issue(it + 1, buf ^ 1);
                asm volatile("cp.async.wait_group 1;" ::: "memory");
            } else {
                asm volatile("cp.async.wait_group 0;" ::: "memory");
            }
            __syncthreads();
            #pragma unroll
            for (int ks = 0; ks < 2; ks++) {
                unsigned afrag[2][2][4];
                int arow = wm * 32 + (lane & 15);
                int acol = ks * 16 + ((lane >> 4) << 3);
                #pragma unroll
                for (int mt = 0; mt < 2; mt++)
                    #pragma unroll
                    for (int p = 0; p < 2; p++)
                        ldsm4(afrag[mt][p],
                              sA_base + (unsigned)(((buf*2 + p)*GBM + arow + mt*16)*ASTRIDE + acol) * 2u);
                int brow = ks * 16 + (lane & 15);
                #pragma unroll
                for (int half = 0; half < 2; half++) {
                    unsigned bfrag[2][4][2];
                    #pragma unroll
                    for (int ngh = 0; ngh < 2; ngh++) {
                        int ng = half * 2 + ngh;
                        int chunk = wn * 8 + ng * 2 + (lane >> 4);
                        #pragma unroll
                        for (int p = 0; p < 2; p++) {
                            unsigned addr = sB_base + (unsigned)((buf*2 + p) * SB_BYTES_TILE
                                          + brow * 256 + ((chunk ^ (brow & 7)) << 4));
                            unsigned r4[4];
                            ldsm4t(r4, addr);
                            bfrag[p][2*ngh][0]   = r4[0]; bfrag[p][2*ngh][1]   = r4[1];
                            bfrag[p][2*ngh+1][0] = r4[2]; bfrag[p][2*ngh+1][1] = r4[3];
                        }
                    }
                    #pragma unroll
                    for (int mt = 0; mt < 2; mt++)
                        #pragma unroll
                        for (int nt = 0; nt < 4; nt++) {
                            float* a = acc[mt][half*4 + nt];
                            mma16816(a, afrag[mt][0], bfrag[0][nt]);
                            mma16816(a, afrag[mt][0], bfrag[1][nt]);
                            mma16816(a, afrag[mt][1], bfrag[0][nt]);
                        }
                }
            }
            __syncthreads();
        }

        // epilogue
        #pragma unroll
        for (int mt = 0; mt < 2; mt++) {
            #pragma unroll
            for (int nt = 0; nt < 8; nt++) {
                int r0 = bm + wm * 32 + mt * 16 + (lane >> 2);
                int c0 = bn + wn * 64 + nt * 8 + ((lane & 3) << 1);
                #pragma unroll
                for (int hh = 0; hh < 2; hh++) {
                    int rr = r0 + hh * 8;
                    #pragma unroll
                    for (int cc = 0; cc < 2; cc++) {
                        int col = c0 + cc;
                        float v = acc[mt][nt][hh*2 + cc] + bias[col];
                        size_t idx = (size_t)rr * N + col;
                        if (EPI == 0) {
                            Cf[idx] = v;
                        } else if (EPI == 1) {
                            Cf[idx] = res[idx] + v;
                        } else {
                            if (EPI == 2) v = fmaxf(v, 0.f);
                            bf16 vh, vl; split2(v, vh, vl);
                            Chi[idx] = vh; Clo[idx] = vl;
                        }
                    }
                }
            }
        }
    }
}

// ---------------- HMMA flash attention (bf16x3) -------------------------------
#define AQ 128
#define AKT 64
#define QSTR 72
#define ASMEM_BYTES (2*128*QSTR*2 + 4*64*QSTR*2 + 256)

__global__ void __launch_bounds__(256, 1) attn_mma_kernel(
    const bf16* __restrict__ qkv_hi, const bf16* __restrict__ qkv_lo,
    const float* __restrict__ amask,
    bf16* __restrict__ ctxhi, bf16* __restrict__ ctxlo)
{
    extern __shared__ __align__(16) char asmem[];
    bf16* sQh = (bf16*)asmem;
    bf16* sQl = sQh + 128*QSTR;
    bf16* sKh = sQl + 128*QSTR;
    bf16* sKl = sKh + 64*QSTR;
    bf16* sVh = sKl + 64*QSTR;
    bf16* sVl = sVh + 64*QSTR;
    float* skm = (float*)(sVl + 64*QSTR);

    const int tid = threadIdx.x, lane = tid & 31, w = tid >> 5;
    const int bh = blockIdx.y, b = bh >> 4, hh = bh & 15;
    const int q0 = blockIdx.x * AQ;
    const float scale = 0.125f;

    const size_t rstr = 3 * Dc;
    const bf16* qh = qkv_hi + (size_t)b * Tc * rstr + hh * HD;
    const bf16* ql = qkv_lo + (size_t)b * Tc * rstr + hh * HD;
    const bf16* kh = qh + Dc;  const bf16* kl = ql + Dc;
    const bf16* vh = qh + 2*Dc; const bf16* vl = ql + 2*Dc;

    #pragma unroll
    for (int j = 0; j < 8; j++) {
        int c = tid + j * 256;
        int p = c >> 10, rem = c & 1023;
        int row = rem >> 3, ch = rem & 7;
        *(uint4*)((p ? sQl : sQh) + row * QSTR + ch * 8) =
            *(const uint4*)((p ? ql : qh) + (size_t)(q0 + row) * rstr + ch * 8);
    }
    __syncthreads();

    const unsigned qb_h = smem_u32(sQh), qb_l = smem_u32(sQl);
    const unsigned kb_h = smem_u32(sKh), kb_l = smem_u32(sKl);
    const unsigned vb_h = smem_u32(sVh), vb_l = smem_u32(sVl);

    unsigned aQh[4][4], aQl[4][4];
    {
        int arow = w * 16 + (lane & 15);
        #pragma unroll
        for (int g = 0; g < 4; g++) {
            int acol = g * 16 + ((lane >> 4) << 3);
            unsigned off = (unsigned)(arow * QSTR + acol) * 2u;
            ldsm4(aQh[g], qb_h + off);
            ldsm4(aQl[g], qb_l + off);
        }
    }

    float acc[8][4];
    #pragma unroll
    for (int nt = 0; nt < 8; nt++)
        #pragma unroll
        for (int e = 0; e < 4; e++) acc[nt][e] = 0.f;
    float m0 = -1e30f, m1 = -1e30f, l0 = 0.f, l1 = 0.f;

    const int qg0 = q0 + w * 16 + (lane >> 2);
    const int ncol = (lane & 3) << 1;
    const int kn_l = (lane & 7) + ((lane >> 4) << 3);
    const int kkoff = ((lane >> 3) & 1) << 3;

    const int nkt = 2 * blockIdx.x + 2;
    for (int kt = 0; kt < nkt; kt++) {
        int kk0 = kt * AKT;
        __syncthreads();
        #pragma unroll
        for (int j = 0; j < 8; j++) {
            int c = tid + j * 256;
            int arr = c >> 9, rem = c & 511;
            int row = rem >> 3, ch = rem & 7;
            const bf16* gp = (arr == 0) ? kh : (arr == 1) ? kl : (arr == 2) ? vh : vl;
            bf16* sp = (arr == 0) ? sKh : (arr == 1) ? sKl : (arr == 2) ? sVh : sVl;
            *(uint4*)(sp + row * QSTR + ch * 8) =
                *(const uint4*)(gp + (size_t)(kk0 + row) * rstr + ch * 8);
        }
        if (tid < 64) skm[tid] = (1.0f - amask[b * Tc + kk0 + tid]) * MASK_BIAS;
        __syncthreads();

        float S[8][4];
        #pragma unroll
        for (int nt = 0; nt < 8; nt++)
            #pragma unroll
            for (int e = 0; e < 4; e++) S[nt][e] = 0.f;

        #pragma unroll
        for (int g = 0; g < 4; g++) {
            unsigned bKh[8][2], bKl[8][2];
            #pragma unroll
            for (int np = 0; np < 4; np++) {
                unsigned off = (unsigned)((np * 16 + kn_l) * QSTR + g * 16 + kkoff) * 2u;
                unsigned r4[4];
                ldsm4(r4, kb_h + off);
                bKh[2*np][0] = r4[0]; bKh[2*np][1] = r4[1];
                bKh[2*np+1][0] = r4[2]; bKh[2*np+1][1] = r4[3];
                ldsm4(r4, kb_l + off);
                bKl[2*np][0] = r4[0]; bKl[2*np][1] = r4[1];
                bKl[2*np+1][0] = r4[2]; bKl[2*np+1][1] = r4[3];
            }
            #pragma unroll
            for (int nt = 0; nt < 8; nt++) {
                mma16816(S[nt], aQh[g], bKh[nt]);
                mma16816(S[nt], aQh[g], bKl[nt]);
                mma16816(S[nt], aQl[g], bKh[nt]);
            }
        }

        float tmax0 = -1e30f, tmax1 = -1e30f;
        #pragma unroll
        for (int nt = 0; nt < 8; nt++) {
            int n0 = kk0 + nt * 8 + ncol;
            float km0 = skm[nt * 8 + ncol], km1 = skm[nt * 8 + ncol + 1];
            float s0 = (n0     <= qg0    ) ? S[nt][0] * scale + km0 : -1e30f;
            float s1 = (n0 + 1 <= qg0    ) ? S[nt][1] * scale + km1 : -1e30f;
            float s2 = (n0     <= qg0 + 8) ? S[nt][2] * scale + km0 : -1e30f;
            float s3 = (n0 + 1 <= qg0 + 8) ? S[nt][3] * scale + km1 : -1e30f;
            S[nt][0] = s0; S[nt][1] = s1; S[nt][2] = s2; S[nt][3] = s3;
            tmax0 = fmaxf(tmax0, fmaxf(s0, s1));
            tmax1 = fmaxf(tmax1, fmaxf(s2, s3));
        }
        tmax0 = fmaxf(tmax0, __shfl_xor_sync(0xffffffffu, tmax0, 1));
        tmax0 = fmaxf(tmax0, __shfl_xor_sync(0xffffffffu, tmax0, 2));
        tmax1 = fmaxf(tmax1, __shfl_xor_sync(0xffffffffu, tmax1, 1));
        tmax1 = fmaxf(tmax1, __shfl_xor_sync(0xffffffffu, tmax1, 2));

        float nm0 = fmaxf(m0, tmax0), nm1 = fmaxf(m1, tmax1);
        float cr0 = __expf(m0 - nm0), cr1 = __expf(m1 - nm1);
        m0 = nm0; m1 = nm1;

        float sum0 = 0.f, sum1 = 0.f;
        #pragma unroll
        for (int nt = 0; nt < 8; nt++) {
            float p0 = __expf(S[nt][0] - m0);
            float p1 = __expf(S[nt][1] - m0);
            float p2 = __expf(S[nt][2] - m1);
            float p3 = __expf(S[nt][3] - m1);
            S[nt][0] = p0; S[nt][1] = p1; S[nt][2] = p2; S[nt][3] = p3;
            sum0 += p0 + p1; sum1 += p2 + p3;
        }
        sum0 += __shfl_xor_sync(0xffffffffu, sum0, 1);
        sum0 += __shfl_xor_sync(0xffffffffu, sum0, 2);
        sum1 += __shfl_xor_sync(0xffffffffu, sum1, 1);
        sum1 += __shfl_xor_sync(0xffffffffu, sum1, 2);
        l0 = l0 * cr0 + sum0;
        l1 = l1 * cr1 + sum1;
        #pragma unroll
        for (int nt = 0; nt < 8; nt++) {
            acc[nt][0] *= cr0; acc[nt][1] *= cr0;
            acc[nt][2] *= cr1; acc[nt][3] *= cr1;
        }

        #pragma unroll
        for (int g = 0; g < 4; g++) {
            unsigned aPh[4], aPl[4];
            packsplit(S[2*g][0],   S[2*g][1],   aPh[0], aPl[0]);
            packsplit(S[2*g][2],   S[2*g][3],   aPh[1], aPl[1]);
            packsplit(S[2*g+1][0], S[2*g+1][1], aPh[2], aPl[2]);
            packsplit(S[2*g+1][2], S[2*g+1][3], aPh[3], aPl[3]);
            unsigned bVh[8][2], bVl[8][2];
            int brow = g * 16 + (lane & 15);
            #pragma unroll
            for (int np = 0; np < 4; np++) {
                int bcol = np * 16 + ((lane >> 4) << 3);
                unsigned off = (unsigned)(brow * QSTR + bcol) * 2u;
                unsigned r4[4];
                ldsm4t(r4, vb_h + off);
                bVh[2*np][0] = r4[0]; bVh[2*np][1] = r4[1];
                bVh[2*np+1][0] = r4[2]; bVh[2*np+1][1] = r4[3];
                ldsm4t(r4, vb_l + off);
                bVl[2*np][0] = r4[0]; bVl[2*np][1] = r4[1];
                bVl[2*np+1][0] = r4[2]; bVl[2*np+1][1] = r4[3];
            }
            #pragma unroll
            for (int nt = 0; nt < 8; nt++) {
                mma16816(acc[nt], aPh, bVh[nt]);
                mma16816(acc[nt], aPh, bVl[nt]);
                mma16816(acc[nt], aPl, bVh[nt]);
            }
        }
    }

    float il0 = 1.0f / l0, il1 = 1.0f / l1;
    int row0 = q0 + w * 16 + (lane >> 2);
    size_t o0 = ((size_t)(b * Tc + row0)) * Dc + hh * HD + ncol;
    size_t o1 = ((size_t)(b * Tc + row0 + 8)) * Dc + hh * HD + ncol;
    #pragma unroll
    for (int nt = 0; nt < 8; nt++) {
        float v0 = acc[nt][0] * il0, v1 = acc[nt][1] * il0;
        float v2 = acc[nt][2] * il1, v3 = acc[nt][3] * il1;
        bf16 h0,lo0,h1,lo1,h2,lo2,h3,lo3;
        split2(v0,h0,lo0); split2(v1,h1,lo1); split2(v2,h2,lo2); split2(v3,h3,lo3);
        *(__nv_bfloat162*)(ctxhi + o0 + nt*8) = __nv_bfloat162(h0, h1);
        *(__nv_bfloat162*)(ctxlo + o0 + nt*8) = __nv_bfloat162(lo0, lo1);
        *(__nv_bfloat162*)(ctxhi + o1 + nt*8) = __nv_bfloat162(h2, h3);
        *(__nv_bfloat162*)(ctxlo + o1 + nt*8) = __nv_bfloat162(lo2, lo3);
    }
}

// ---------------- launch -----------------------------------------------------
extern "C" void kernel_launch(void* const* d_in, const int* in_sizes, int n_in,
                              void* d_out, int out_size)
{
    const float* emb    = (const float*)d_in[0];
    const float* amask  = (const float*)d_in[1];
    const float* ln1_w  = (const float*)d_in[2];
    const float* ln1_b  = (const float*)d_in[3];
    const float* attn_w = (const float*)d_in[4];
    const float* attn_b = (const float*)d_in[5];
    const float* proj_w = (const float*)d_in[6];
    const float* proj_b = (const float*)d_in[7];
    const float* ln2_w  = (const float*)d_in[8];
    const float* ln2_b  = (const float*)d_in[9];
    const float* fc_w   = (const float*)d_in[10];
    const float* fc_b   = (const float*)d_in[11];
    const float* fcp_w  = (const float*)d_in[12];
    const float* fcp_b  = (const float*)d_in[13];
    const float* lnf_w  = (const float*)d_in[14];
    const float* lnf_b  = (const float*)d_in[15];
    float* out = (float*)d_out;

    float* h;
    bf16 *qhi, *qlo, *xhi, *xlo, *chi, *clo, *ahi, *alo;
    bf16 *wq_h, *wq_l, *wp_h, *wp_l, *wf_h, *wf_l, *wg_h, *wg_l;
    cudaGetSymbolAddress((void**)&h,    g_h);
    cudaGetSymbolAddress((void**)&qhi,  g_qhi);  cudaGetSymbolAddress((void**)&qlo, g_qlo);
    cudaGetSymbolAddress((void**)&xhi,  g_xhi);  cudaGetSymbolAddress((void**)&xlo, g_xlo);
    cudaGetSymbolAddress((void**)&chi,  g_chi);  cudaGetSymbolAddress((void**)&clo, g_clo);
    cudaGetSymbolAddress((void**)&ahi,  g_ahi);  cudaGetSymbolAddress((void**)&alo, g_alo);
    cudaGetSymbolAddress((void**)&wq_h, g_wqkv_hi); cudaGetSymbolAddress((void**)&wq_l, g_wqkv_lo);
    cudaGetSymbolAddress((void**)&wp_h, g_wprj_hi); cudaGetSymbolAddress((void**)&wp_l, g_wprj_lo);
    cudaGetSymbolAddress((void**)&wf_h, g_wfc_hi);  cudaGetSymbolAddress((void**)&wf_l, g_wfc_lo);
    cudaGetSymbolAddress((void**)&wg_h, g_wfp_hi);  cudaGetSymbolAddress((void**)&wg_l, g_wfp_lo);

    cudaFuncSetAttribute(gemm3_kernel<0>, cudaFuncAttributeMaxDynamicSharedMemorySize, GSMEM_BYTES);
    cudaFuncSetAttribute(gemm3_kernel<1>, cudaFuncAttributeMaxDynamicSharedMemorySize, GSMEM_BYTES);
    cudaFuncSetAttribute(gemm3_kernel<2>, cudaFuncAttributeMaxDynamicSharedMemorySize, GSMEM_BYTES);
    cudaFuncSetAttribute(gemm3_kernel<3>, cudaFuncAttributeMaxDynamicSharedMemorySize, GSMEM_BYTES);
    cudaFuncSetAttribute(attn_mma_kernel, cudaFuncAttributeMaxDynamicSharedMemorySize, ASMEM_BYTES);

    // weight splits [K,N] hi/lo
    { int n4 = Lc*Dc*3*Dc/4; split4_kernel<<<(n4+255)/256, 256>>>(attn_w, wq_h, wq_l, n4); }
    { int n4 = Lc*Dc*Dc/4;   split4_kernel<<<(n4+255)/256, 256>>>(proj_w, wp_h, wp_l, n4); }
    { int n4 = Lc*Dc*Ic/4;   split4_kernel<<<(n4+255)/256, 256>>>(fc_w,   wf_h, wf_l, n4); }
    { int n4 = Lc*Ic*Dc/4;   split4_kernel<<<(n4+255)/256, 256>>>(fcp_w,  wg_h, wg_l, n4); }

    for (int l = 0; l < Lc; l++) {
        const float* hin = (l == 0) ? emb : h;   // layer-0 reads embeds directly
        // x = ln1(hin) -> split
        ln_kernel<true><<<ROWS, 256>>>(hin, ln1_w + (size_t)l*Dc, ln1_b + (size_t)l*Dc,
                                       nullptr, xhi, xlo);
        // qkv = x @ attn_w + attn_b  -> bf16 hi/lo
        gemm3_kernel<3><<<GPERS, 256, GSMEM_BYTES>>>(
            xhi, xlo, wq_h + (size_t)l*Dc*3*Dc, wq_l + (size_t)l*Dc*3*Dc,
            attn_b + (size_t)l*3*Dc, nullptr, nullptr, qhi, qlo,
            ROWS, 3*Dc, Dc);
        // ctx = attention(qkv) -> split
        attn_mma_kernel<<<dim3(Tc/AQ, Bc*Hc), 256, ASMEM_BYTES>>>(qhi, qlo, amask, chi, clo);
        // h = hin + ctx @ proj_w + proj_b
        gemm3_kernel<1><<<GPERS, 256, GSMEM_BYTES>>>(
            chi, clo, wp_h + (size_t)l*Dc*Dc, wp_l + (size_t)l*Dc*Dc,
            proj_b + (size_t)l*Dc, hin, h, nullptr, nullptr,
            ROWS, Dc, Dc);
        // x = ln2(h) -> split
        ln_kernel<true><<<ROWS, 256>>>(h, ln2_w + (size_t)l*Dc, ln2_b + (size_t)l*Dc,
                                       nullptr, xhi, xlo);
        // act = relu(x @ fc_w + fc_b) -> split
        gemm3_kernel<2><<<GPERS, 256, GSMEM_BYTES>>>(
            xhi, xlo, wf_h + (size_t)l*Dc*Ic, wf_l + (size_t)l*Dc*Ic,
            fc_b + (size_t)l*Ic, nullptr, nullptr, ahi, alo,
            ROWS, Ic, Dc);
        // h = h + act @ fcp_w + fcp_b
        gemm3_kernel<1><<<GPERS, 256, GSMEM_BYTES>>>(
            ahi, alo, wg_h + (size_t)l*Ic*Dc, wg_l + (size_t)l*Ic*Dc,
            fcp_b + (size_t)l*Dc, h, h, nullptr, nullptr,
            ROWS, Dc, Ic);
    }
    // out = ln_f(h) (fp32)
    ln_kernel<false><<<ROWS, 256>>>(h, lnf_w, lnf_b, out, nullptr, nullptr);
}